// round 3
// baseline (speedup 1.0000x reference)
#include <cuda_runtime.h>

#define B_      128
#define N_      200
#define T_      360
#define P_      400
#define STRIDE_ 25
#define PT_     100   // patterns per block tile
#define PITCH_  204   // padded row pitch (floats): conflict-free float4 LDS

__device__ float d_npat[P_ * N_];
__device__ int   d_topidx[P_ * 3];
__device__ float d_topval[P_ * 3];
__device__ float d_maskgraph[N_ * N_];
__device__ float d_fs[B_ * P_];
__device__ float d_A[P_ * 2];

// ---------------------------------------------------------------- zero scratch
__global__ void zero_kernel(float* out) {
    int i = blockIdx.x * blockDim.x + threadIdx.x;
    if (i < N_ * N_) d_maskgraph[i] = 0.f;
    if (i < 2) out[256 + i] = 0.f;   // norm accumulator + rec
}

// ------------------------------------------------- patterns: normalize + top3
__global__ void pat_kernel(const float* __restrict__ patterns, float* out) {
    int p   = blockIdx.x;
    int tid = threadIdx.x;   // 64 threads
    __shared__ float red[64];
    float s = 0.f;
    for (int k = tid; k < N_; k += 64) { float v = patterns[p * N_ + k]; s += v * v; }
    red[tid] = s; __syncthreads();
    for (int off = 32; off > 0; off >>= 1) {
        if (tid < off) red[tid] += red[tid + off];
        __syncthreads();
    }
    float ssq = red[0];
    float rs  = rsqrtf(ssq + 1e-9f);
    for (int k = tid; k < N_; k += 64) d_npat[p * N_ + k] = patterns[p * N_ + k] * rs;
    if (tid == 0) {
        int idx[3]; float val[3];
        for (int r = 0; r < 3; r++) {
            float best = -1.f; int bi = 0;
            for (int k = 0; k < N_; k++) {
                bool used = false;
                for (int q = 0; q < r; q++) if (idx[q] == k) used = true;
                if (used) continue;
                float a = fabsf(patterns[p * N_ + k]);   // same ranking as |npat|
                if (a > best) { best = a; bi = k; }
            }
            idx[r] = bi; val[r] = patterns[p * N_ + bi] * rs;
        }
        for (int r = 0; r < 3; r++) { d_topidx[p * 3 + r] = idx[r]; d_topval[p * 3 + r] = val[r]; }
        float tn = sqrtf(val[0]*val[0] + val[1]*val[1] + val[2]*val[2]);
        float pn = sqrtf(ssq) * rs;                      // ||npat||
        float d  = 1.f - tn / pn;
        atomicAdd(&out[256], d * d * (1.f / 800.f));
        for (int i = 0; i < 3; i++)
            for (int j = 0; j < 3; j++)
                atomicAdd(&d_maskgraph[idx[i] * N_ + idx[j]], 1.f);
    }
}

// ------------------------------------------------------------ main fused GEMM
// grid (B, 4). Per block: scores for 100 patterns x valid windows of one b,
// fused strided max-pool + sum. Only windows w < sap are computed.
__global__ void __launch_bounds__(256) main_kernel(const float* __restrict__ x,
                                                   const int* __restrict__ length) {
    extern __shared__ float sm[];
    float* s_pat = sm;                        // PT_ * PITCH_
    float* s_x   = sm + PT_ * PITCH_;         // 50 * PITCH_ (also reused as score buf)
    float* s_rn  = s_x + 50 * PITCH_;         // 64
    float* s_fs  = s_rn + 64;                 // PT_

    int b    = blockIdx.x;
    int p0   = blockIdx.y * PT_;
    int tid  = threadIdx.x;
    int sap  = length[b] / STRIDE_;
    int vlen = sap * STRIDE_;

    for (int i = tid; i < PT_ * N_; i += 256) {
        int p = i / N_, k = i - p * N_;
        s_pat[p * PITCH_ + k] = d_npat[(p0 + p) * N_ + k];
    }
    if (tid < PT_) s_fs[tid] = 0.f;
    __syncthreads();

    int  tcol = tid % 25;
    int  pg   = tid / 25;
    bool act  = tid < 250;

    for (int w = 0; w < sap; w += 2) {
        int t0 = w * STRIDE_;
        // load x chunk [n][tt] -> s_x[tt][n], masking invalid t to exact 0
        for (int i = tid; i < N_ * 50; i += 256) {
            int n = i / 50, tt = i - n * 50;
            int t = t0 + tt;
            float v = (t < vlen) ? x[((size_t)b * N_ + n) * T_ + t] : 0.f;
            s_x[tt * PITCH_ + n] = v;
        }
        __syncthreads();
        // per-t frame norms (warp per t)
        int wid = tid >> 5, lane = tid & 31;
        for (int tt = wid; tt < 50; tt += 8) {
            float s = 0.f;
            for (int k = lane; k < N_; k += 32) { float v = s_x[tt * PITCH_ + k]; s += v * v; }
            for (int off = 16; off > 0; off >>= 1) s += __shfl_xor_sync(0xffffffffu, s, off);
            if (lane == 0) s_rn[tt] = rsqrtf(s + 1e-9f);
        }
        __syncthreads();
        // register-tiled GEMM: thread = 10 patterns x 2 t (same slot in 2 windows)
        float acc0[10], acc1[10];
        float rn0 = 0.f, rn1 = 0.f;
        if (act) {
            #pragma unroll
            for (int i = 0; i < 10; i++) { acc0[i] = 0.f; acc1[i] = 0.f; }
            const float4* xr0 = (const float4*)&s_x[tcol * PITCH_];
            const float4* xr1 = (const float4*)&s_x[(tcol + 25) * PITCH_];
            const float4* pr  = (const float4*)&s_pat[pg * 10 * PITCH_];
            #pragma unroll 2
            for (int kq = 0; kq < N_ / 4; kq++) {
                float4 a = xr0[kq];
                float4 c = xr1[kq];
                #pragma unroll
                for (int i = 0; i < 10; i++) {
                    float4 q = pr[i * (PITCH_ / 4) + kq];
                    acc0[i] += q.x * a.x + q.y * a.y + q.z * a.z + q.w * a.w;
                    acc1[i] += q.x * c.x + q.y * c.y + q.z * c.z + q.w * c.w;
                }
            }
            rn0 = s_rn[tcol];
            rn1 = s_rn[tcol + 25];
        }
        __syncthreads();          // all reads of s_x done; reuse as score buffer
        if (act) {
            #pragma unroll
            for (int i = 0; i < 10; i++) {
                int p = pg * 10 + i;
                s_x[p * 50 + tcol]      = acc0[i] * rn0;
                s_x[p * 50 + 25 + tcol] = acc1[i] * rn1;
            }
        }
        __syncthreads();
        if (tid < PT_) {          // window max + accumulate (invalid window == 0)
            float m0 = -1e30f, m1 = -1e30f;
            #pragma unroll
            for (int j = 0; j < 25; j++) {
                m0 = fmaxf(m0, s_x[tid * 50 + j]);
                m1 = fmaxf(m1, s_x[tid * 50 + 25 + j]);
            }
            s_fs[tid] += m0 + m1;
        }
        __syncthreads();
    }
    if (tid < PT_) d_fs[b * P_ + p0 + tid] = s_fs[tid] / (float)sap;
}

// ----------------------------- A[p,c] = sum_{9 pairs} rp_i rp_j / (mg+eps) * W
__global__ void a_kernel(const float* __restrict__ W) {
    int p = blockIdx.x * blockDim.x + threadIdx.x;
    if (p >= P_) return;
    int idx[3]; float val[3];
    for (int r = 0; r < 3; r++) { idx[r] = d_topidx[p * 3 + r]; val[r] = d_topval[p * 3 + r]; }
    float a0 = 0.f, a1 = 0.f;
    for (int i = 0; i < 3; i++)
        for (int j = 0; j < 3; j++) {
            int   nm   = idx[i] * N_ + idx[j];
            float coef = val[i] * val[j] / (d_maskgraph[nm] + 1e-9f);
            a0 += coef * W[nm * 2 + 0];
            a1 += coef * W[nm * 2 + 1];
        }
    d_A[p * 2 + 0] = a0;
    d_A[p * 2 + 1] = a1;
}

// ------------------------------------------------ out[b,c] = fs[b,:]·A[:,c]+b
__global__ void out_kernel(const float* __restrict__ bcls, float* out) {
    int tid = blockIdx.x * blockDim.x + threadIdx.x;
    if (tid >= B_ * 2) return;
    int b = tid >> 1, c = tid & 1;
    float s = bcls[c];
    for (int p = 0; p < P_; p++) s += d_fs[b * P_ + p] * d_A[p * 2 + c];
    out[tid] = s;
}

extern "C" void kernel_launch(void* const* d_in, const int* in_sizes, int n_in,
                              void* d_out, int out_size) {
    const float* x        = (const float*)d_in[0];
    const int*   length   = (const int*)d_in[1];
    const float* patterns = (const float*)d_in[2];
    const float* W        = (const float*)d_in[3];
    const float* bcls     = (const float*)d_in[4];
    float* out = (float*)d_out;

    zero_kernel<<<(N_ * N_ + 255) / 256, 256>>>(out);
    pat_kernel<<<P_, 64>>>(patterns, out);

    size_t smem = (size_t)(PT_ * PITCH_ + 50 * PITCH_ + 64 + PT_) * sizeof(float);
    cudaFuncSetAttribute(main_kernel, cudaFuncAttributeMaxDynamicSharedMemorySize, (int)smem);
    dim3 grid(B_, P_ / PT_);
    main_kernel<<<grid, 256, smem>>>(x, length);

    a_kernel<<<2, 256>>>(W);
    out_kernel<<<1, 256>>>(bcls, out);
}

// round 6
// speedup vs baseline: 2.3428x; 2.3428x over previous
#include <cuda_runtime.h>

#define B_      128
#define N_      200
#define T_      360
#define P_      400
#define PPAD_   512
#define STRIDE_ 25
#define NSTRIP_ 4
#define BLKS_PER_STRIP_ 37

__device__ float d_npatP[PPAD_ * N_];     // normalized patterns, rows >=400 zero
__device__ int   d_topidx[P_ * 3];
__device__ float d_topval[P_ * 3];
__device__ float d_maskgraph[N_ * N_];
__device__ float d_fs[B_ * P_];           // accumulated window-max sums
__device__ float d_rn[B_ * T_];           // per-frame rsqrt norm (0 where invalid)
__device__ int   d_units[1024];           // b | (wpair<<8)
__device__ int   d_nunits;

__device__ __forceinline__ unsigned f2tf32(float f) {
    unsigned u;
    asm("cvt.rna.tf32.f32 %0, %1;" : "=r"(u) : "f"(f));
    return u;
}

// ---------------------------------------------------------------- zero scratch
__global__ void zero_kernel(float* out) {
    int i = blockIdx.x * blockDim.x + threadIdx.x;
    if (i < B_ * P_) d_fs[i] = 0.f;
    if (i < N_ * N_) d_maskgraph[i] = 0.f;
    if (i < (PPAD_ - P_) * N_) d_npatP[P_ * N_ + i] = 0.f;
    if (i < 2) out[256 + i] = 0.f;   // norm accumulator + rec
}

// ------------------------------------------------- patterns: normalize + top3
__global__ void pat_kernel(const float* __restrict__ patterns, float* out) {
    int p   = blockIdx.x;
    int tid = threadIdx.x;   // 64 threads
    __shared__ float red[64];
    float s = 0.f;
    for (int k = tid; k < N_; k += 64) { float v = patterns[p * N_ + k]; s += v * v; }
    red[tid] = s; __syncthreads();
    for (int off = 32; off > 0; off >>= 1) {
        if (tid < off) red[tid] += red[tid + off];
        __syncthreads();
    }
    float ssq = red[0];
    float rs  = rsqrtf(ssq + 1e-9f);
    for (int k = tid; k < N_; k += 64) d_npatP[p * N_ + k] = patterns[p * N_ + k] * rs;
    if (tid == 0) {
        int idx[3]; float val[3];
        for (int r = 0; r < 3; r++) {
            float best = -1.f; int bi = 0;
            for (int k = 0; k < N_; k++) {
                bool used = false;
                for (int q = 0; q < r; q++) if (idx[q] == k) used = true;
                if (used) continue;
                float a = fabsf(patterns[p * N_ + k]);
                if (a > best) { best = a; bi = k; }
            }
            idx[r] = bi; val[r] = patterns[p * N_ + bi] * rs;
        }
        for (int r = 0; r < 3; r++) { d_topidx[p * 3 + r] = idx[r]; d_topval[p * 3 + r] = val[r]; }
        float tn = sqrtf(val[0]*val[0] + val[1]*val[1] + val[2]*val[2]);
        float pn = sqrtf(ssq) * rs;
        float d  = 1.f - tn / pn;
        atomicAdd(&out[256], d * d * (1.f / 800.f));
        for (int i = 0; i < 3; i++)
            for (int j = 0; j < 3; j++)
                atomicAdd(&d_maskgraph[idx[i] * N_ + idx[j]], 1.f);
    }
}

// ------------------------------------ frame norms: rn[b][t], 0 where t invalid
__global__ void rn_kernel(const float* __restrict__ x, const int* __restrict__ length) {
    int b    = blockIdx.x;
    int vlen = (length[b] / STRIDE_) * STRIDE_;
    for (int t = threadIdx.x; t < T_; t += blockDim.x) {
        float rn = 0.f;
        if (t < vlen) {
            float s = 0.f;
            #pragma unroll 4
            for (int n = 0; n < N_; n++) {
                float v = x[((size_t)b * N_ + n) * T_ + t];
                s += v * v;
            }
            rn = rsqrtf(s + 1e-9f);
        }
        d_rn[b * T_ + t] = rn;
    }
}

// -------------------------------------------- build balanced work-unit list
__global__ void unit_kernel(const int* __restrict__ length) {
    __shared__ int pre[B_];
    int tid = threadIdx.x;   // 128 threads
    int sap = length[tid] / STRIDE_;
    int cnt = (sap + 1) / 2;
    pre[tid] = cnt;
    __syncthreads();
    if (tid == 0) {
        int off = 0;
        for (int i = 0; i < B_; i++) { int c = pre[i]; pre[i] = off; off += c; }
        d_nunits = off;
    }
    __syncthreads();
    int off = pre[tid];
    for (int j = 0; j < cnt; j++) d_units[off + j] = tid | (j << 8);
}

// -------------------------------------------------- main tensor-core kernel
// 148 persistent blocks: strip = bid%4 (128 patterns), 37 blocks share units.
// Unit = (b, window pair): 50 t cols (padded to 56), full K=200.
#define S_PATF 0                    // 8 mtiles * 25 ksteps * 32 lanes * 4 = 25600 floats
#define S_B    25600                // 200 k * 56 cols = 11200 floats
#define S_RNU  36800                // 56 + pad
#define SMEMF  36864

__global__ void __launch_bounds__(256, 1) mma_kernel(const float* __restrict__ x) {
    extern __shared__ float sm[];
    int tid   = threadIdx.x;
    int wid   = tid >> 5;
    int lane  = tid & 31;
    int gid   = lane >> 2;
    int tig   = lane & 3;
    int strip = blockIdx.x & (NSTRIP_ - 1);
    int widx  = blockIdx.x >> 2;        // 0..36
    int p0    = strip * 128;

    // ---- one-time: patterns -> fragment-order tf32 smem ----
    for (int d = tid; d < 8 * 25 * 32; d += 256) {
        int mt = d / (25 * 32);
        int r1 = d % (25 * 32);
        int ks = r1 >> 5;
        int ln = r1 & 31;
        int pr = p0 + mt * 16 + (ln >> 2);
        int kb = ks * 8 + (ln & 3);
        float4 v;
        v.x = __uint_as_float(f2tf32(d_npatP[pr * N_ + kb]));
        v.y = __uint_as_float(f2tf32(d_npatP[(pr + 8) * N_ + kb]));
        v.z = __uint_as_float(f2tf32(d_npatP[pr * N_ + kb + 4]));
        v.w = __uint_as_float(f2tf32(d_npatP[(pr + 8) * N_ + kb + 4]));
        ((float4*)sm)[d] = v;
    }

    int nunits = d_nunits;
    for (int ui = widx; ui < nunits; ui += BLKS_PER_STRIP_) {
        __syncthreads();   // previous iter's smem reads complete
        int e  = d_units[ui];
        int b  = e & 255;
        int t0 = (e >> 8) * 50;

        // stage x chunk (tf32-rounded) into s_B[k=n][col=tt], zero cols 50..55
        float* sB = sm + S_B;
        for (int i = tid; i < N_ * 50; i += 256) {
            int n  = i / 50, tt = i - n * 50;
            float f = x[((size_t)b * N_ + n) * T_ + t0 + tt];
            sB[n * 56 + tt] = __uint_as_float(f2tf32(f));
        }
        for (int i = tid; i < N_ * 6; i += 256) {
            int n = i / 6, c = 50 + i - n * 6;
            sB[n * 56 + c] = 0.f;
        }
        if (tid < 56) sm[S_RNU + tid] = (tid < 50) ? d_rn[b * T_ + t0 + tid] : 0.f;
        __syncthreads();

        // ---- MMA: warp = one 16-row m-tile x 7 n-tiles, K=200 (25 steps) ----
        float acc[7][4];
        #pragma unroll
        for (int nt = 0; nt < 7; nt++)
            #pragma unroll
            for (int c = 0; c < 4; c++) acc[nt][c] = 0.f;

        const float4* aP = ((const float4*)sm) + wid * 25 * 32;
        #pragma unroll 5
        for (int ks = 0; ks < 25; ks++) {
            float4 af = aP[ks * 32 + lane];
            unsigned a0 = __float_as_uint(af.x), a1 = __float_as_uint(af.y);
            unsigned a2 = __float_as_uint(af.z), a3 = __float_as_uint(af.w);
            const float* br0 = sB + (ks * 8 + tig) * 56 + gid;
            const float* br1 = br0 + 4 * 56;
            #pragma unroll
            for (int nt = 0; nt < 7; nt++) {
                unsigned b0 = __float_as_uint(br0[nt * 8]);
                unsigned b1 = __float_as_uint(br1[nt * 8]);
                asm volatile(
                    "mma.sync.aligned.m16n8k8.row.col.f32.tf32.tf32.f32 "
                    "{%0,%1,%2,%3}, {%4,%5,%6,%7}, {%8,%9}, {%0,%1,%2,%3};"
                    : "+f"(acc[nt][0]), "+f"(acc[nt][1]), "+f"(acc[nt][2]), "+f"(acc[nt][3])
                    : "r"(a0), "r"(a1), "r"(a2), "r"(a3), "r"(b0), "r"(b1));
            }
        }

        // ---- epilogue: scale by rn, window max, reduce over lane quad ----
        float m0a = -1e30f, m1a = -1e30f, m0b = -1e30f, m1b = -1e30f;
        #pragma unroll
        for (int nt = 0; nt < 7; nt++) {
            #pragma unroll
            for (int c = 0; c < 2; c++) {
                int col = nt * 8 + 2 * tig + c;
                if (col < 50) {
                    float rn = sm[S_RNU + col];
                    float va = acc[nt][c]     * rn;   // row gid
                    float vb = acc[nt][c + 2] * rn;   // row gid+8
                    if (col < 25) { m0a = fmaxf(m0a, va); m0b = fmaxf(m0b, vb); }
                    else          { m1a = fmaxf(m1a, va); m1b = fmaxf(m1b, vb); }
                }
            }
        }
        #pragma unroll
        for (int off = 1; off <= 2; off <<= 1) {
            m0a = fmaxf(m0a, __shfl_xor_sync(0xffffffffu, m0a, off));
            m1a = fmaxf(m1a, __shfl_xor_sync(0xffffffffu, m1a, off));
            m0b = fmaxf(m0b, __shfl_xor_sync(0xffffffffu, m0b, off));
            m1b = fmaxf(m1b, __shfl_xor_sync(0xffffffffu, m1b, off));
        }
        if (tig == 0) {
            int pa = p0 + wid * 16 + gid;
            if (pa < P_)     atomicAdd(&d_fs[b * P_ + pa],     m0a + m1a);
            if (pa + 8 < P_) atomicAdd(&d_fs[b * P_ + pa + 8], m0b + m1b);
        }
    }
}

// ------------------------------------- tail: A[p,c] then out = fs/sap . A + b
__global__ void tail_kernel(const float* __restrict__ W, const float* __restrict__ bcls,
                            const int* __restrict__ length, float* out) {
    __shared__ float sA[P_ * 2];
    int tid = threadIdx.x;
    for (int p = tid; p < P_; p += 256) {
        int idx[3]; float val[3];
        for (int r = 0; r < 3; r++) { idx[r] = d_topidx[p * 3 + r]; val[r] = d_topval[p * 3 + r]; }
        float a0 = 0.f, a1 = 0.f;
        for (int i = 0; i < 3; i++)
            for (int j = 0; j < 3; j++) {
                int   nm   = idx[i] * N_ + idx[j];
                float coef = val[i] * val[j] / (d_maskgraph[nm] + 1e-9f);
                a0 += coef * W[nm * 2 + 0];
                a1 += coef * W[nm * 2 + 1];
            }
        sA[p * 2 + 0] = a0;
        sA[p * 2 + 1] = a1;
    }
    __syncthreads();
    if (tid < B_ * 2) {
        int b = tid >> 1, c = tid & 1;
        float inv = 1.f / (float)(length[b] / STRIDE_);
        float s = 0.f;
        #pragma unroll 4
        for (int p = 0; p < P_; p++) s += d_fs[b * P_ + p] * sA[p * 2 + c];
        out[tid] = bcls[c] + s * inv;
    }
}

extern "C" void kernel_launch(void* const* d_in, const int* in_sizes, int n_in,
                              void* d_out, int out_size) {
    const float* x        = (const float*)d_in[0];
    const int*   length   = (const int*)d_in[1];
    const float* patterns = (const float*)d_in[2];
    const float* W        = (const float*)d_in[3];
    const float* bcls     = (const float*)d_in[4];
    float* out = (float*)d_out;

    zero_kernel<<<(B_ * P_ + 255) / 256, 256>>>(out);
    pat_kernel<<<P_, 64>>>(patterns, out);
    rn_kernel<<<B_, 256>>>(x, length);
    unit_kernel<<<1, B_>>>(length);

    size_t smem = SMEMF * sizeof(float);
    cudaFuncSetAttribute(mma_kernel, cudaFuncAttributeMaxDynamicSharedMemorySize, (int)smem);
    mma_kernel<<<NSTRIP_ * BLKS_PER_STRIP_, 256, smem>>>(x);

    tail_kernel<<<1, 256>>>(W, bcls, length, out);
}

// round 7
// speedup vs baseline: 2.8293x; 1.2077x over previous
#include <cuda_runtime.h>

#define B_      128
#define N_      200
#define T_      360
#define P_      400
#define PPAD_   512
#define STRIDE_ 25
#define NSTRIP_ 4
#define BLKS_PER_STRIP_ 37
#define COLS_   56
#define KS_H_   13          // ksteps per half (K padded 200 -> 208)

__device__ float d_npatP[PPAD_ * N_];     // normalized patterns, rows >=400 stay zero
__device__ int   d_topidx[P_ * 3];
__device__ float d_topval[P_ * 3];
__device__ float d_maskgraph[N_ * N_];
__device__ float d_fs[B_ * P_];           // accumulated window-max sums
__device__ float d_rn[B_ * T_];           // per-frame rsqrt norm (0 where invalid)
__device__ int   d_units[1024];           // b | (wpair<<8)
__device__ int   d_nunits;

__device__ __forceinline__ unsigned f2tf32(float f) {
    unsigned u;
    asm("cvt.rna.tf32.f32 %0, %1;" : "=r"(u) : "f"(f));
    return u;
}

// ---------------------------------------------------------------- zero scratch
__global__ void zero_kernel(float* out) {
    int i = blockIdx.x * blockDim.x + threadIdx.x;
    if (i < B_ * P_) d_fs[i] = 0.f;
    if (i < N_ * N_) d_maskgraph[i] = 0.f;
    if (i < 2) out[256 + i] = 0.f;   // norm accumulator + rec
}

// ------------------------- fused prep: pat (0..399) | rn (400..527) | unit (528)
__global__ void __launch_bounds__(128) prep_kernel(const float* __restrict__ x,
                                                   const int* __restrict__ length,
                                                   const float* __restrict__ patterns,
                                                   float* out) {
    __shared__ float red[128];
    __shared__ float av[128];
    __shared__ int   ai[128];
    __shared__ int   sidx[3];
    __shared__ int   pre[B_];
    int bid = blockIdx.x;
    int tid = threadIdx.x;

    if (bid < P_) {
        // ---------------- pattern: normalize + parallel top-3 ----------------
        int p = bid;
        float s = 0.f;
        for (int k = tid; k < N_; k += 128) { float v = patterns[p * N_ + k]; s += v * v; }
        red[tid] = s; __syncthreads();
        for (int off = 64; off > 0; off >>= 1) {
            if (tid < off) red[tid] += red[tid + off];
            __syncthreads();
        }
        float ssq = red[0];
        float rs  = rsqrtf(ssq + 1e-9f);
        for (int k = tid; k < N_; k += 128) d_npatP[p * N_ + k] = patterns[p * N_ + k] * rs;

        int have[3];
        for (int r = 0; r < 3; r++) {
            float best = -1.f; int bi = N_;
            for (int k = tid; k < N_; k += 128) {
                bool used = false;
                for (int q = 0; q < r; q++) used |= (k == have[q]);
                if (used) continue;
                float a = fabsf(patterns[p * N_ + k]);
                if (a > best || (a == best && k < bi)) { best = a; bi = k; }
            }
            av[tid] = best; ai[tid] = bi; __syncthreads();
            for (int off = 64; off > 0; off >>= 1) {
                if (tid < off) {
                    if (av[tid + off] > av[tid] ||
                        (av[tid + off] == av[tid] && ai[tid + off] < ai[tid])) {
                        av[tid] = av[tid + off]; ai[tid] = ai[tid + off];
                    }
                }
                __syncthreads();
            }
            if (tid == 0) sidx[r] = ai[0];
            __syncthreads();
            have[r] = sidx[r];
        }
        if (tid == 0) {
            float val[3];
            for (int r = 0; r < 3; r++) {
                val[r] = patterns[p * N_ + have[r]] * rs;
                d_topidx[p * 3 + r] = have[r];
                d_topval[p * 3 + r] = val[r];
            }
            float tn = sqrtf(val[0]*val[0] + val[1]*val[1] + val[2]*val[2]);
            float pn = sqrtf(ssq) * rs;
            float d  = 1.f - tn / pn;
            atomicAdd(&out[256], d * d * (1.f / 800.f));
            for (int i = 0; i < 3; i++)
                for (int j = 0; j < 3; j++)
                    atomicAdd(&d_maskgraph[have[i] * N_ + have[j]], 1.f);
        }
    } else if (bid < P_ + B_) {
        // ------------------------ frame norms for one b -----------------------
        int b    = bid - P_;
        int vlen = (length[b] / STRIDE_) * STRIDE_;
        if (tid < T_ / 4) {
            float4 acc = make_float4(0.f, 0.f, 0.f, 0.f);
            const float* xb = x + (size_t)b * N_ * T_ + tid * 4;
            #pragma unroll 4
            for (int n = 0; n < N_; n++) {
                float4 v = *(const float4*)(xb + (size_t)n * T_);
                acc.x += v.x * v.x; acc.y += v.y * v.y;
                acc.z += v.z * v.z; acc.w += v.w * v.w;
            }
            int t = tid * 4;
            d_rn[b * T_ + t + 0] = (t + 0 < vlen) ? rsqrtf(acc.x + 1e-9f) : 0.f;
            d_rn[b * T_ + t + 1] = (t + 1 < vlen) ? rsqrtf(acc.y + 1e-9f) : 0.f;
            d_rn[b * T_ + t + 2] = (t + 2 < vlen) ? rsqrtf(acc.z + 1e-9f) : 0.f;
            d_rn[b * T_ + t + 3] = (t + 3 < vlen) ? rsqrtf(acc.w + 1e-9f) : 0.f;
        }
    } else {
        // --------------------------- unit list --------------------------------
        int sap = length[tid] / STRIDE_;
        int cnt = (sap + 1) / 2;
        pre[tid] = cnt;
        __syncthreads();
        if (tid == 0) {
            int off = 0;
            for (int i = 0; i < B_; i++) { int c = pre[i]; pre[i] = off; off += c; }
            d_nunits = off;
        }
        __syncthreads();
        int off = pre[tid];
        for (int j = 0; j < cnt; j++) d_units[off + j] = tid | (j << 8);
    }
}

// -------------------------------------------------- main tensor-core kernel
// 148 blocks x 512 threads. strip = bid%4 (128 patterns). 16 warps = 8 mtiles
// x 2 k-halves; A fragments live in registers for the whole unit loop.
#define S_B    0                     // 208 * 56 floats
#define S_RED  (208 * COLS_)         // 256 * 28 floats
#define S_RNU  (S_RED + 256 * 28)    // 50 (+pad)
#define SMEMF  (S_RNU + 64)

__global__ void __launch_bounds__(512, 1) mma_kernel(const float* __restrict__ x) {
    extern __shared__ float sm[];
    float* sB   = sm + S_B;
    float* sRed = sm + S_RED;
    float* sRn  = sm + S_RNU;

    int tid   = threadIdx.x;
    int wid   = tid >> 5;
    int lane  = tid & 31;
    int gid   = lane >> 2;
    int tig   = lane & 3;
    int strip = blockIdx.x & (NSTRIP_ - 1);
    int widx  = blockIdx.x >> 2;        // 0..36
    int p0    = strip * 128;
    int mt    = wid & 7;
    int khalf = wid >> 3;
    int ksb   = khalf * KS_H_;          // 0 or 13

    // ---- one-time: this warp's A fragments -> registers (tf32) ----
    unsigned aF[KS_H_][4];
    {
        int pr = p0 + mt * 16 + gid;
        const float* r0 = d_npatP + (size_t)pr * N_;
        const float* r1 = r0 + 8 * N_;
        #pragma unroll
        for (int ks = 0; ks < KS_H_; ks++) {
            int kk = (ksb + ks) * 8 + tig;
            aF[ks][0] = (kk     < N_) ? f2tf32(r0[kk])     : 0u;
            aF[ks][1] = (kk     < N_) ? f2tf32(r1[kk])     : 0u;
            aF[ks][2] = (kk + 4 < N_) ? f2tf32(r0[kk + 4]) : 0u;
            aF[ks][3] = (kk + 4 < N_) ? f2tf32(r1[kk + 4]) : 0u;
        }
    }
    // zero k-pad rows 200..207 once (staging never touches them)
    for (int i = tid; i < 8 * COLS_; i += 512) sB[N_ * COLS_ + i] = 0.f;

    int nunits = d_nunits;
    for (int ui = widx; ui < nunits; ui += BLKS_PER_STRIP_) {
        __syncthreads();   // previous iter's smem reads complete
        int e  = d_units[ui];
        int b  = e & 255;
        int t0 = (e >> 8) * 50;

        // stage x chunk (tf32-rounded) into sB[k=n][col=tt]
        const float* xb = x + ((size_t)b * N_) * T_ + t0;
        for (int i = tid; i < N_ * 50; i += 512) {
            int n = i / 50, tt = i - n * 50;
            sB[n * COLS_ + tt] = __uint_as_float(f2tf32(xb[(size_t)n * T_ + tt]));
        }
        if (tid < 50) sRn[tid] = d_rn[b * T_ + t0 + tid];
        __syncthreads();

        // ---- MMA: warp = 1 mtile x 7 ntiles x its 13 ksteps ----
        float acc[7][4];
        #pragma unroll
        for (int nt = 0; nt < 7; nt++)
            #pragma unroll
            for (int c = 0; c < 4; c++) acc[nt][c] = 0.f;

        const float* bBase = sB + (ksb * 8 + tig) * COLS_ + gid;
        #pragma unroll
        for (int ks = 0; ks < KS_H_; ks++) {
            const float* br0 = bBase + ks * 8 * COLS_;
            const float* br1 = br0 + 4 * COLS_;
            #pragma unroll
            for (int nt = 0; nt < 7; nt++) {
                unsigned b0 = __float_as_uint(br0[nt * 8]);
                unsigned b1 = __float_as_uint(br1[nt * 8]);
                asm volatile(
                    "mma.sync.aligned.m16n8k8.row.col.f32.tf32.tf32.f32 "
                    "{%0,%1,%2,%3}, {%4,%5,%6,%7}, {%8,%9}, {%0,%1,%2,%3};"
                    : "+f"(acc[nt][0]), "+f"(acc[nt][1]), "+f"(acc[nt][2]), "+f"(acc[nt][3])
                    : "r"(aF[ks][0]), "r"(aF[ks][1]), "r"(aF[ks][2]), "r"(aF[ks][3]),
                      "r"(b0), "r"(b1));
            }
        }

        // ---- cross-k-half reduction via smem ----
        if (khalf == 1) {
            float* dst = sRed + (tid & 255) * 28;
            #pragma unroll
            for (int nt = 0; nt < 7; nt++)
                *(float4*)(dst + nt * 4) =
                    make_float4(acc[nt][0], acc[nt][1], acc[nt][2], acc[nt][3]);
        }
        __syncthreads();
        if (khalf == 0) {
            const float* src = sRed + tid * 28;
            float m0a = -1e30f, m1a = -1e30f, m0b = -1e30f, m1b = -1e30f;
            #pragma unroll
            for (int nt = 0; nt < 7; nt++) {
                float4 pv = *(const float4*)(src + nt * 4);
                float d0 = acc[nt][0] + pv.x;
                float d1 = acc[nt][1] + pv.y;
                float d2 = acc[nt][2] + pv.z;
                float d3 = acc[nt][3] + pv.w;
                #pragma unroll
                for (int c = 0; c < 2; c++) {
                    int col = nt * 8 + 2 * tig + c;
                    if (col < 50) {
                        float rn = sRn[col];
                        float va = (c ? d1 : d0) * rn;   // row gid
                        float vb = (c ? d3 : d2) * rn;   // row gid+8
                        if (col < 25) { m0a = fmaxf(m0a, va); m0b = fmaxf(m0b, vb); }
                        else          { m1a = fmaxf(m1a, va); m1b = fmaxf(m1b, vb); }
                    }
                }
            }
            #pragma unroll
            for (int off = 1; off <= 2; off <<= 1) {
                m0a = fmaxf(m0a, __shfl_xor_sync(0xffffffffu, m0a, off));
                m1a = fmaxf(m1a, __shfl_xor_sync(0xffffffffu, m1a, off));
                m0b = fmaxf(m0b, __shfl_xor_sync(0xffffffffu, m0b, off));
                m1b = fmaxf(m1b, __shfl_xor_sync(0xffffffffu, m1b, off));
            }
            if (tig == 0) {
                int pa = p0 + mt * 16 + gid;
                if (pa < P_)     atomicAdd(&d_fs[b * P_ + pa],     m0a + m1a);
                if (pa + 8 < P_) atomicAdd(&d_fs[b * P_ + pa + 8], m0b + m1b);
            }
        }
    }
}

// ------------------------------------- tail: A[p,c] then out = fs/sap . A + b
__global__ void tail_kernel(const float* __restrict__ W, const float* __restrict__ bcls,
                            const int* __restrict__ length, float* out) {
    __shared__ float sA[P_ * 2];
    int tid = threadIdx.x;
    for (int p = tid; p < P_; p += 256) {
        int idx[3]; float val[3];
        for (int r = 0; r < 3; r++) { idx[r] = d_topidx[p * 3 + r]; val[r] = d_topval[p * 3 + r]; }
        float a0 = 0.f, a1 = 0.f;
        for (int i = 0; i < 3; i++)
            for (int j = 0; j < 3; j++) {
                int   nm   = idx[i] * N_ + idx[j];
                float coef = val[i] * val[j] / (d_maskgraph[nm] + 1e-9f);
                a0 += coef * W[nm * 2 + 0];
                a1 += coef * W[nm * 2 + 1];
            }
        sA[p * 2 + 0] = a0;
        sA[p * 2 + 1] = a1;
    }
    __syncthreads();
    if (tid < B_ * 2) {
        int b = tid >> 1, c = tid & 1;
        float inv = 1.f / (float)(length[b] / STRIDE_);
        float s = 0.f;
        #pragma unroll 4
        for (int p = 0; p < P_; p++) s += d_fs[b * P_ + p] * sA[p * 2 + c];
        out[tid] = bcls[c] + s * inv;
    }
}

extern "C" void kernel_launch(void* const* d_in, const int* in_sizes, int n_in,
                              void* d_out, int out_size) {
    const float* x        = (const float*)d_in[0];
    const int*   length   = (const int*)d_in[1];
    const float* patterns = (const float*)d_in[2];
    const float* W        = (const float*)d_in[3];
    const float* bcls     = (const float*)d_in[4];
    float* out = (float*)d_out;

    zero_kernel<<<(B_ * P_ + 255) / 256, 256>>>(out);
    prep_kernel<<<P_ + B_ + 1, 128>>>(x, length, patterns, out);

    size_t smem = SMEMF * sizeof(float);
    cudaFuncSetAttribute(mma_kernel, cudaFuncAttributeMaxDynamicSharedMemorySize, (int)smem);
    mma_kernel<<<NSTRIP_ * BLKS_PER_STRIP_, 512, smem>>>(x);

    tail_kernel<<<1, 256>>>(W, bcls, length, out);
}